// round 7
// baseline (speedup 1.0000x reference)
#include <cuda_runtime.h>
#include <cstdint>

#ifndef NEG_INF_F
#define NEG_INF_F __int_as_float(0xff800000)
#endif

#define NPB 256          // nodes per block == threads per block
#define EDGE_CAP 9216    // smem staging capacity in floats (36 KB)

// Exact strict-'>' insertion of (x, j) into the running top-4.
// Ties keep the earlier (smaller) edge index, matching the reference.
__device__ __forceinline__ void ins4(float x, int j,
                                     float& v0, float& v1, float& v2, float& v3,
                                     int& i0, int& i1, int& i2, int& i3)
{
    if (x > v3) {
        if (x > v1) {
            if (x > v0) {
                v3 = v2; i3 = i2;
                v2 = v1; i2 = i1;
                v1 = v0; i1 = i0;
                v0 = x;  i0 = j;
            } else {
                v3 = v2; i3 = i2;
                v2 = v1; i2 = i1;
                v1 = x;  i1 = j;
            }
        } else {
            if (x > v2) {
                v3 = v2; i3 = i2;
                v2 = x;  i2 = j;
            } else {
                v3 = x;  i3 = j;
            }
        }
    }
}

// Scan [s, e) reading buf[j - off] (off % 4 == 0 so j's mod-4 alignment is
// preserved in buf). Quad-max fast-reject, exact insertion on hit.
__device__ __forceinline__ void scan_seg(
    const float* __restrict__ buf, int off, int s, int e,
    float& v0, float& v1, float& v2, float& v3,
    int& i0, int& i1, int& i2, int& i3)
{
    int j = s;
    int head_end = (s + 3) & ~3;
    if (head_end > e) head_end = e;
    for (; j < head_end; ++j)
        ins4(buf[j - off], j, v0, v1, v2, v3, i0, i1, i2, i3);

    const float4* bv = reinterpret_cast<const float4*>(buf);
    for (; j + 8 <= e; j += 8) {
        int q = (j - off) >> 2;
        float4 a = bv[q];
        float4 b = bv[q + 1];
        float ma = fmaxf(fmaxf(a.x, a.y), fmaxf(a.z, a.w));
        float mb = fmaxf(fmaxf(b.x, b.y), fmaxf(b.z, b.w));
        if (ma > v3) {
            ins4(a.x, j + 0, v0, v1, v2, v3, i0, i1, i2, i3);
            ins4(a.y, j + 1, v0, v1, v2, v3, i0, i1, i2, i3);
            ins4(a.z, j + 2, v0, v1, v2, v3, i0, i1, i2, i3);
            ins4(a.w, j + 3, v0, v1, v2, v3, i0, i1, i2, i3);
        }
        if (mb > v3) {
            ins4(b.x, j + 4, v0, v1, v2, v3, i0, i1, i2, i3);
            ins4(b.y, j + 5, v0, v1, v2, v3, i0, i1, i2, i3);
            ins4(b.z, j + 6, v0, v1, v2, v3, i0, i1, i2, i3);
            ins4(b.w, j + 7, v0, v1, v2, v3, i0, i1, i2, i3);
        }
    }
    for (; j + 4 <= e; j += 4) {
        float4 a = bv[(j - off) >> 2];
        float ma = fmaxf(fmaxf(a.x, a.y), fmaxf(a.z, a.w));
        if (ma > v3) {
            ins4(a.x, j + 0, v0, v1, v2, v3, i0, i1, i2, i3);
            ins4(a.y, j + 1, v0, v1, v2, v3, i0, i1, i2, i3);
            ins4(a.z, j + 2, v0, v1, v2, v3, i0, i1, i2, i3);
            ins4(a.w, j + 3, v0, v1, v2, v3, i0, i1, i2, i3);
        }
    }
    for (; j < e; ++j)
        ins4(buf[j - off], j, v0, v1, v2, v3, i0, i1, i2, i3);
}

__global__ void __launch_bounds__(NPB) segment_top4_staged_kernel(
    const int* __restrict__ row_ptr,
    const float* __restrict__ scores,
    float* __restrict__ vals_out,   // [N,4] float32
    float* __restrict__ idxf_out,   // [N,4] float32 (index values; exact < 2^24)
    int n_nodes)
{
    __shared__ float sbuf[EDGE_CAP];

    int node0 = blockIdx.x * NPB;
    int node_end = node0 + NPB;
    if (node_end > n_nodes) node_end = n_nodes;

    // Block's contiguous edge range; align start down to a float4 boundary so
    // smem offsets preserve global mod-4 alignment.
    int r0 = __ldg(row_ptr + node0);
    int r1 = __ldg(row_ptr + node_end);
    int base = r0 & ~3;
    int total = r1 - base;
    bool staged = (total <= EDGE_CAP);   // uniform across the block

    if (staged) {
        // Coalesced cooperative copy: full float4s, then <=3 scalar remainder.
        const float4* g4 = reinterpret_cast<const float4*>(scores + base);
        float4* s4 = reinterpret_cast<float4*>(sbuf);
        int n4 = total >> 2;
        for (int t = threadIdx.x; t < n4; t += NPB)
            s4[t] = __ldg(g4 + t);
        int rem_start = n4 << 2;
        for (int t = rem_start + threadIdx.x; t < total; t += NPB)
            sbuf[t] = __ldg(scores + base + t);
        __syncthreads();
    }

    int i = node0 + threadIdx.x;
    if (i >= n_nodes) return;

    int s = __ldg(row_ptr + i);
    int e = __ldg(row_ptr + i + 1);

    float v0 = NEG_INF_F, v1 = NEG_INF_F, v2 = NEG_INF_F, v3 = NEG_INF_F;
    int   i0 = -1, i1 = -1, i2 = -1, i3 = -1;

    if (staged)
        scan_seg(sbuf, base, s, e, v0, v1, v2, v3, i0, i1, i2, i3);
    else
        scan_seg(scores, 0, s, e, v0, v1, v2, v3, i0, i1, i2, i3);

    reinterpret_cast<float4*>(vals_out)[i] = make_float4(v0, v1, v2, v3);
    reinterpret_cast<float4*>(idxf_out)[i] =
        make_float4((float)i0, (float)i1, (float)i2, (float)i3);
}

extern "C" void kernel_launch(void* const* d_in, const int* in_sizes, int n_in,
                              void* d_out, int out_size)
{
    // row_ptr is the smaller input (N+1) vs edge_scores (E).
    int a = in_sizes[0], b = (n_in > 1) ? in_sizes[1] : 0;
    int rp_slot = (n_in > 1 && b < a) ? 1 : 0;
    const int*   row_ptr = (const int*)d_in[rp_slot];
    const float* scores  = (const float*)d_in[1 - rp_slot];
    long long n = (long long)in_sizes[rp_slot] - 1;

    // Single-dtype (float32) output: vals [N,4] then idx-as-float [N,4].
    float* vals_out = (float*)d_out;
    float* idxf_out = vals_out + n * 4;

    int blocks = (int)((n + NPB - 1) / NPB);
    segment_top4_staged_kernel<<<blocks, NPB>>>(row_ptr, scores, vals_out, idxf_out, (int)n);
}